// round 10
// baseline (speedup 1.0000x reference)
#include <cuda_runtime.h>
#include <cuda_fp16.h>
#include <cstdint>

#define NUM_USERS 100000
#define NUM_ITEMS 50000
#define DIM 64
#define NUM_REL 5
#define TCOLS (NUM_REL * DIM)      // 320
#define WCOLS (TCOLS + 8)          // 328: +5 bias cols +3 zero pad
#define NTILES (WCOLS / 8)         // 41
#define SPITCH 328                 // smem tile pitch in halves (656 B, 16B-mult)

typedef unsigned long long ull;

__device__ __half g_Ti[(size_t)NUM_ITEMS * TCOLS];          // 32 MB fp16
__device__ __half g_uh[(size_t)NUM_USERS * DIM];            // 12.8 MB fp16
__device__ __half g_ih[(size_t)NUM_ITEMS * DIM];            // 6.4 MB fp16
__device__ uint2  g_WpF[NTILES * 4 * 32];                   // B fragments, 42 KB
__device__ float  g_bi[(size_t)NUM_ITEMS * 8];              // stride 8
__device__ int    g_idx64;

// ---------------------------------------------------------------------------
// f32x2 helpers
// ---------------------------------------------------------------------------
__device__ __forceinline__ void fma2(ull& d, ull a, ull b) {
    asm("fma.rn.f32x2 %0, %1, %2, %0;" : "+l"(d) : "l"(a), "l"(b));
}
__device__ __forceinline__ ull pack2(float x, float y) {
    ull p; asm("mov.b64 %0, {%1, %2};" : "=l"(p) : "f"(x), "f"(y)); return p;
}
__device__ __forceinline__ float2 unpack2(ull p) {
    float2 r; asm("mov.b64 {%0, %1}, %2;" : "=f"(r.x), "=f"(r.y) : "l"(p)); return r;
}
__device__ __forceinline__ ull h2f2(unsigned int h2) {
    float2 f = __half22float2(*(const __half2*)&h2);
    return pack2(f.x, f.y);
}

// ---------------------------------------------------------------------------
// prep: detect index width; u, i -> fp16 (float4-vectorized); pack W+b into
// B-fragment order (see R9 comment).
// ---------------------------------------------------------------------------
__device__ __forceinline__ float wp_elem(const float* W, const float* b,
                                         int col, int k) {
    if (col < TCOLS) {
        int r = col >> 6, c = col & 63;
        return W[(size_t)r * DIM * DIM + (size_t)k * DIM + c];
    }
    int rb = col - TCOLS;
    return (rb < NUM_REL) ? b[(size_t)rb * DIM + k] : 0.0f;
}

__global__ void prep_kernel(const float* __restrict__ uf,
                            const float* __restrict__ itf,
                            const float* __restrict__ W,
                            const float* __restrict__ b,
                            const void* __restrict__ eu) {
    int gid = blockIdx.x * blockDim.x + threadIdx.x;
    if (gid == 0) {
        const int* p = (const int*)eu;
        int is64 = 1;
        #pragma unroll
        for (int j = 1; j < 16; j += 2)
            if (p[j] != 0) is64 = 0;
        g_idx64 = is64;
    }
    if (gid < NUM_USERS * DIM / 4) {               // u: float4 -> 2x half2
        float4 v = __ldg((const float4*)uf + gid);
        uint2 h;
        __half2 h0 = __floats2half2_rn(v.x, v.y);
        __half2 h1 = __floats2half2_rn(v.z, v.w);
        h.x = *(unsigned*)&h0; h.y = *(unsigned*)&h1;
        ((uint2*)g_uh)[gid] = h;
    }
    if (gid < NUM_ITEMS * DIM / 4) {               // i: float4 -> 2x half2
        float4 v = __ldg((const float4*)itf + gid);
        uint2 h;
        __half2 h0 = __floats2half2_rn(v.x, v.y);
        __half2 h1 = __floats2half2_rn(v.z, v.w);
        h.x = *(unsigned*)&h0; h.y = *(unsigned*)&h1;
        ((uint2*)g_ih)[gid] = h;
    }
    if (gid < NTILES * 4 * 32) {                   // B fragment pack
        int lane = gid & 31;
        int ks   = (gid >> 5) & 3;
        int nt   = gid >> 7;
        int g = lane >> 2, t = lane & 3;
        int col = nt * 8 + g;
        int k0  = ks * 16 + t * 2;
        __half2 b0 = __floats2half2_rn(wp_elem(W, b, col, k0),
                                       wp_elem(W, b, col, k0 + 1));
        __half2 b1 = __floats2half2_rn(wp_elem(W, b, col, k0 + 8),
                                       wp_elem(W, b, col, k0 + 9));
        uint2 fr;
        fr.x = *(unsigned*)&b0;
        fr.y = *(unsigned*)&b1;
        g_WpF[gid] = fr;
    }
}

// ---------------------------------------------------------------------------
// Tensor-core precompute: [Ti | bi] = ih @ Wp^T via mma m16n8k16.
// One warp: 16 items x 328 cols. Ti staged in smem, then coalesced STG.128.
// ---------------------------------------------------------------------------
__device__ __forceinline__ void mma16816(float& c0, float& c1, float& c2, float& c3,
                                         unsigned a0, unsigned a1, unsigned a2, unsigned a3,
                                         unsigned b0, unsigned b1) {
    asm volatile(
        "mma.sync.aligned.m16n8k16.row.col.f32.f16.f16.f32 "
        "{%0,%1,%2,%3}, {%4,%5,%6,%7}, {%8,%9}, {%0,%1,%2,%3};"
        : "+f"(c0), "+f"(c1), "+f"(c2), "+f"(c3)
        : "r"(a0), "r"(a1), "r"(a2), "r"(a3), "r"(b0), "r"(b1));
}

__global__ __launch_bounds__(128) void mma_precompute_kernel() {
    __shared__ __half sT[4 * 16 * SPITCH];          // 4 warps x 16 rows, 41 KB
    int wband = (threadIdx.x >> 5) * 16 * SPITCH;
    int warp = (blockIdx.x * blockDim.x + threadIdx.x) >> 5;
    if (warp >= NUM_ITEMS / 16) return;
    int lane = threadIdx.x & 31;
    int g = lane >> 2;
    int t = lane & 3;
    int item0 = warp * 16;

    const __half* ihr0 = g_ih + (size_t)(item0 + g) * DIM;
    const __half* ihr1 = g_ih + (size_t)(item0 + g + 8) * DIM;
    unsigned a[4][4];
    #pragma unroll
    for (int ks = 0; ks < 4; ks++) {
        int k0 = ks * 16 + t * 2;
        a[ks][0] = *(const unsigned*)(ihr0 + k0);
        a[ks][1] = *(const unsigned*)(ihr1 + k0);
        a[ks][2] = *(const unsigned*)(ihr0 + k0 + 8);
        a[ks][3] = *(const unsigned*)(ihr1 + k0 + 8);
    }

    #pragma unroll 4
    for (int nt = 0; nt < NTILES; nt++) {
        float c0 = 0.f, c1 = 0.f, c2 = 0.f, c3 = 0.f;
        const uint2* bf = g_WpF + nt * 4 * 32 + lane;
        #pragma unroll
        for (int ks = 0; ks < 4; ks++) {
            uint2 bb = __ldg(bf + ks * 32);
            mma16816(c0, c1, c2, c3,
                     a[ks][0], a[ks][1], a[ks][2], a[ks][3], bb.x, bb.y);
        }
        if (nt < TCOLS / 8) {                       // stage in smem (no conflicts)
            __half2 h01 = __floats2half2_rn(c0, c1);
            __half2 h23 = __floats2half2_rn(c2, c3);
            int col = nt * 8 + t * 2;
            *(unsigned*)(sT + wband + g * SPITCH + col)       = *(unsigned*)&h01;
            *(unsigned*)(sT + wband + (g + 8) * SPITCH + col) = *(unsigned*)&h23;
        } else {                                    // bias tile -> g_bi direct
            *(float2*)(g_bi + (size_t)(item0 + g) * 8 + t * 2)     = make_float2(c0, c1);
            *(float2*)(g_bi + (size_t)(item0 + g + 8) * 8 + t * 2) = make_float2(c2, c3);
        }
    }
    __syncwarp();

    // Coalesced writeback: 16 rows x 320 halves = 640 uint4, contiguous in Ti.
    uint4* dst = (uint4*)(g_Ti + (size_t)item0 * TCOLS);
    #pragma unroll
    for (int j = lane; j < 16 * (TCOLS / 8); j += 32) {
        int row = j / (TCOLS / 8);
        int col = j - row * (TCOLS / 8);
        dst[j] = *(const uint4*)(sT + wband + row * SPITCH + col * 8);
    }
}

// ---------------------------------------------------------------------------
// Edge kernel: 8 lanes per edge (R7 structure), f32x2 arithmetic.
// out[e][r] = dot(u[user], Ti[item][r]) + bi[item][r]
// ---------------------------------------------------------------------------
__global__ void edge_kernel(const void* __restrict__ edge_u,
                            const void* __restrict__ edge_i,
                            float* __restrict__ out,
                            int E) {
    int gid = blockIdx.x * blockDim.x + threadIdx.x;
    int e  = gid >> 3;
    int sl = gid & 7;
    if (e >= E) return;

    long long user, item;
    if (g_idx64) {
        user = __ldg((const long long*)edge_u + e);
        item = __ldg((const long long*)edge_i + e);
    } else {
        user = (long long)__ldg((const int*)edge_u + e);
        item = (long long)__ldg((const int*)edge_i + e);
    }

    uint4 uv = __ldg((const uint4*)g_uh + (size_t)user * 8 + sl);
    ull uf0 = h2f2(uv.x), uf1 = h2f2(uv.y), uf2 = h2f2(uv.z), uf3 = h2f2(uv.w);

    const uint4* trow = (const uint4*)g_Ti + (size_t)item * (NUM_REL * 8);

    float s[NUM_REL];
    #pragma unroll
    for (int r = 0; r < NUM_REL; r++) {
        uint4 tv = __ldg(trow + r * 8 + sl);
        ull acc = 0;
        fma2(acc, uf0, h2f2(tv.x));
        fma2(acc, uf1, h2f2(tv.y));
        fma2(acc, uf2, h2f2(tv.z));
        fma2(acc, uf3, h2f2(tv.w));
        float2 p = unpack2(acc);
        s[r] = p.x + p.y;
    }

    #pragma unroll
    for (int off = 4; off > 0; off >>= 1) {
        #pragma unroll
        for (int r = 0; r < NUM_REL; r++)
            s[r] += __shfl_xor_sync(0xffffffffu, s[r], off);
    }

    if (sl < NUM_REL) {
        float v = (sl == 0) ? s[0] : (sl == 1) ? s[1] : (sl == 2) ? s[2]
                : (sl == 3) ? s[3] : s[4];
        v += __ldg(g_bi + (size_t)item * 8 + sl);
        out[(size_t)e * NUM_REL + sl] = v;
    }
}

// ---------------------------------------------------------------------------
extern "C" void kernel_launch(void* const* d_in, const int* in_sizes, int n_in,
                              void* d_out, int out_size) {
    const float* uf  = (const float*)d_in[0];
    const float* itf = (const float*)d_in[1];
    const void*  eu  = d_in[2];
    const void*  ei  = d_in[3];
    const float* W   = (const float*)d_in[4];
    const float* b   = (const float*)d_in[5];
    int E = in_sizes[2];

    {
        int n = NUM_USERS * DIM / 4;                // largest prep range
        prep_kernel<<<(n + 255) / 256, 256>>>(uf, itf, W, b, eu);
    }
    {
        int warps = NUM_ITEMS / 16;                 // 3125
        int blocks = (warps + 3) / 4;
        mma_precompute_kernel<<<blocks, 128>>>();
    }
    {
        long long total_threads = (long long)E * 8;
        int eblocks = (int)((total_threads + 255) / 256);
        edge_kernel<<<eblocks, 256>>>(eu, ei, (float*)d_out, E);
    }
}

// round 11
// speedup vs baseline: 1.0797x; 1.0797x over previous
#include <cuda_runtime.h>
#include <cuda_fp16.h>
#include <cstdint>

#define NUM_USERS 100000
#define NUM_ITEMS 50000
#define DIM 64
#define NUM_REL 5
#define TCOLS (NUM_REL * DIM)      // 320
#define WCOLS (TCOLS + 8)          // 328: +5 bias cols +3 zero pad
#define NTILES (WCOLS / 8)         // 41

__device__ __half g_Ti[(size_t)NUM_ITEMS * TCOLS];          // 32 MB fp16
__device__ __half g_uh[(size_t)NUM_USERS * DIM];            // 12.8 MB fp16
__device__ __half g_ih[(size_t)NUM_ITEMS * DIM];            // 6.4 MB fp16
__device__ uint2  g_WpF[NTILES * 4 * 32];                   // B fragments, 42 KB
__device__ float  g_bi[(size_t)NUM_ITEMS * 8];              // stride 8
__device__ int    g_idx64;

// ---------------------------------------------------------------------------
// prep (R10, measured 10.7us): detect index width; u, i -> fp16 (float4);
// pack W+b into B-fragment order.
// ---------------------------------------------------------------------------
__device__ __forceinline__ float wp_elem(const float* W, const float* b,
                                         int col, int k) {
    if (col < TCOLS) {
        int r = col >> 6, c = col & 63;
        return W[(size_t)r * DIM * DIM + (size_t)k * DIM + c];
    }
    int rb = col - TCOLS;
    return (rb < NUM_REL) ? b[(size_t)rb * DIM + k] : 0.0f;
}

__global__ void prep_kernel(const float* __restrict__ uf,
                            const float* __restrict__ itf,
                            const float* __restrict__ W,
                            const float* __restrict__ b,
                            const void* __restrict__ eu) {
    int gid = blockIdx.x * blockDim.x + threadIdx.x;
    if (gid == 0) {
        const int* p = (const int*)eu;
        int is64 = 1;
        #pragma unroll
        for (int j = 1; j < 16; j += 2)
            if (p[j] != 0) is64 = 0;
        g_idx64 = is64;
    }
    if (gid < NUM_USERS * DIM / 4) {               // u: float4 -> 2x half2
        float4 v = __ldg((const float4*)uf + gid);
        uint2 h;
        __half2 h0 = __floats2half2_rn(v.x, v.y);
        __half2 h1 = __floats2half2_rn(v.z, v.w);
        h.x = *(unsigned*)&h0; h.y = *(unsigned*)&h1;
        ((uint2*)g_uh)[gid] = h;
    }
    if (gid < NUM_ITEMS * DIM / 4) {               // i: float4 -> 2x half2
        float4 v = __ldg((const float4*)itf + gid);
        uint2 h;
        __half2 h0 = __floats2half2_rn(v.x, v.y);
        __half2 h1 = __floats2half2_rn(v.z, v.w);
        h.x = *(unsigned*)&h0; h.y = *(unsigned*)&h1;
        ((uint2*)g_ih)[gid] = h;
    }
    if (gid < NTILES * 4 * 32) {                   // B fragment pack
        int lane = gid & 31;
        int ks   = (gid >> 5) & 3;
        int nt   = gid >> 7;
        int g = lane >> 2, t = lane & 3;
        int col = nt * 8 + g;
        int k0  = ks * 16 + t * 2;
        __half2 b0 = __floats2half2_rn(wp_elem(W, b, col, k0),
                                       wp_elem(W, b, col, k0 + 1));
        __half2 b1 = __floats2half2_rn(wp_elem(W, b, col, k0 + 8),
                                       wp_elem(W, b, col, k0 + 9));
        uint2 fr;
        fr.x = *(unsigned*)&b0;
        fr.y = *(unsigned*)&b1;
        g_WpF[gid] = fr;
    }
}

// ---------------------------------------------------------------------------
// Tensor-core precompute (R9, measured): [Ti | bi] = ih @ Wp^T, mma m16n8k16.
// One warp: 16 items x 328 cols (41 n-tiles; tile 40 -> g_bi).
// ---------------------------------------------------------------------------
__device__ __forceinline__ void mma16816(float& c0, float& c1, float& c2, float& c3,
                                         unsigned a0, unsigned a1, unsigned a2, unsigned a3,
                                         unsigned b0, unsigned b1) {
    asm volatile(
        "mma.sync.aligned.m16n8k16.row.col.f32.f16.f16.f32 "
        "{%0,%1,%2,%3}, {%4,%5,%6,%7}, {%8,%9}, {%0,%1,%2,%3};"
        : "+f"(c0), "+f"(c1), "+f"(c2), "+f"(c3)
        : "r"(a0), "r"(a1), "r"(a2), "r"(a3), "r"(b0), "r"(b1));
}

__global__ __launch_bounds__(128) void mma_precompute_kernel() {
    int warp = (blockIdx.x * blockDim.x + threadIdx.x) >> 5;
    if (warp >= NUM_ITEMS / 16) return;
    int lane = threadIdx.x & 31;
    int g = lane >> 2;
    int t = lane & 3;
    int item0 = warp * 16;

    const __half* ihr0 = g_ih + (size_t)(item0 + g) * DIM;
    const __half* ihr1 = g_ih + (size_t)(item0 + g + 8) * DIM;
    unsigned a[4][4];
    #pragma unroll
    for (int ks = 0; ks < 4; ks++) {
        int k0 = ks * 16 + t * 2;
        a[ks][0] = *(const unsigned*)(ihr0 + k0);
        a[ks][1] = *(const unsigned*)(ihr1 + k0);
        a[ks][2] = *(const unsigned*)(ihr0 + k0 + 8);
        a[ks][3] = *(const unsigned*)(ihr1 + k0 + 8);
    }

    #pragma unroll 4
    for (int nt = 0; nt < NTILES; nt++) {
        float c0 = 0.f, c1 = 0.f, c2 = 0.f, c3 = 0.f;
        const uint2* bf = g_WpF + nt * 4 * 32 + lane;
        #pragma unroll
        for (int ks = 0; ks < 4; ks++) {
            uint2 bb = __ldg(bf + ks * 32);
            mma16816(c0, c1, c2, c3,
                     a[ks][0], a[ks][1], a[ks][2], a[ks][3], bb.x, bb.y);
        }
        if (nt < TCOLS / 8) {
            __half2 h01 = __floats2half2_rn(c0, c1);
            __half2 h23 = __floats2half2_rn(c2, c3);
            int col = nt * 8 + t * 2;
            *(unsigned*)(g_Ti + (size_t)(item0 + g) * TCOLS + col)     = *(unsigned*)&h01;
            *(unsigned*)(g_Ti + (size_t)(item0 + g + 8) * TCOLS + col) = *(unsigned*)&h23;
        } else {                                   // bias tile -> g_bi
            *(float2*)(g_bi + (size_t)(item0 + g) * 8 + t * 2)     = make_float2(c0, c1);
            *(float2*)(g_bi + (size_t)(item0 + g + 8) * 8 + t * 2) = make_float2(c2, c3);
        }
    }
}

// ---------------------------------------------------------------------------
// Edge kernel (R7, measured 117us): 8 lanes per edge, lane owns one uint4.
// out[e][r] = dot(u[user], Ti[item][r]) + bi[item][r]
// ---------------------------------------------------------------------------
__device__ __forceinline__ float dot8h(uint4 a, uint4 b) {
    float2 a0 = __half22float2(*(const __half2*)&a.x);
    float2 b0 = __half22float2(*(const __half2*)&b.x);
    float2 a1 = __half22float2(*(const __half2*)&a.y);
    float2 b1 = __half22float2(*(const __half2*)&b.y);
    float2 a2 = __half22float2(*(const __half2*)&a.z);
    float2 b2 = __half22float2(*(const __half2*)&b.z);
    float2 a3 = __half22float2(*(const __half2*)&a.w);
    float2 b3 = __half22float2(*(const __half2*)&b.w);
    float s = a0.x * b0.x;
    s = fmaf(a0.y, b0.y, s);
    s = fmaf(a1.x, b1.x, s);
    s = fmaf(a1.y, b1.y, s);
    s = fmaf(a2.x, b2.x, s);
    s = fmaf(a2.y, b2.y, s);
    s = fmaf(a3.x, b3.x, s);
    s = fmaf(a3.y, b3.y, s);
    return s;
}

__global__ void edge_kernel(const void* __restrict__ edge_u,
                            const void* __restrict__ edge_i,
                            float* __restrict__ out,
                            int E) {
    int gid = blockIdx.x * blockDim.x + threadIdx.x;
    int e  = gid >> 3;
    int sl = gid & 7;
    if (e >= E) return;

    long long user, item;
    if (g_idx64) {
        user = __ldg((const long long*)edge_u + e);
        item = __ldg((const long long*)edge_i + e);
    } else {
        user = (long long)__ldg((const int*)edge_u + e);
        item = (long long)__ldg((const int*)edge_i + e);
    }

    uint4 uv = __ldg((const uint4*)g_uh + (size_t)user * 8 + sl);
    const uint4* trow = (const uint4*)g_Ti + (size_t)item * (NUM_REL * 8);

    float a0 = dot8h(uv, __ldg(trow + 0 * 8 + sl));
    float a1 = dot8h(uv, __ldg(trow + 1 * 8 + sl));
    float a2 = dot8h(uv, __ldg(trow + 2 * 8 + sl));
    float a3 = dot8h(uv, __ldg(trow + 3 * 8 + sl));
    float a4 = dot8h(uv, __ldg(trow + 4 * 8 + sl));

    #pragma unroll
    for (int off = 4; off > 0; off >>= 1) {
        a0 += __shfl_xor_sync(0xffffffffu, a0, off);
        a1 += __shfl_xor_sync(0xffffffffu, a1, off);
        a2 += __shfl_xor_sync(0xffffffffu, a2, off);
        a3 += __shfl_xor_sync(0xffffffffu, a3, off);
        a4 += __shfl_xor_sync(0xffffffffu, a4, off);
    }

    if (sl < NUM_REL) {
        float v = (sl == 0) ? a0 : (sl == 1) ? a1 : (sl == 2) ? a2
                : (sl == 3) ? a3 : a4;
        v += __ldg(g_bi + (size_t)item * 8 + sl);
        out[(size_t)e * NUM_REL + sl] = v;
    }
}

// ---------------------------------------------------------------------------
extern "C" void kernel_launch(void* const* d_in, const int* in_sizes, int n_in,
                              void* d_out, int out_size) {
    const float* uf  = (const float*)d_in[0];
    const float* itf = (const float*)d_in[1];
    const void*  eu  = d_in[2];
    const void*  ei  = d_in[3];
    const float* W   = (const float*)d_in[4];
    const float* b   = (const float*)d_in[5];
    int E = in_sizes[2];

    {
        int n = NUM_USERS * DIM / 4;                // largest prep range
        prep_kernel<<<(n + 255) / 256, 256>>>(uf, itf, W, b, eu);
    }
    {
        int warps = NUM_ITEMS / 16;                 // 3125
        int blocks = (warps + 3) / 4;
        mma_precompute_kernel<<<blocks, 128>>>();
    }
    {
        long long total_threads = (long long)E * 8;
        int eblocks = (int)((total_threads + 255) / 256);
        edge_kernel<<<eblocks, 256>>>(eu, ei, (float*)d_out, E);
    }
}